// round 16
// baseline (speedup 1.0000x reference)
#include <cuda_runtime.h>
#include <math_constants.h>

#define NCLS   20
#define NBOX   400
#define SORTN  512
#define IMGW   1333.0f
#define IMGH   800.0f
#define TOPK   100
#define NSEL   (NCLS * TOPK)     // 2000
#define NW     13                // 400 bits -> 13 u32 words
#define NTILE  13                // 13 x 32 rows = 416 >= 400
#define SENTK  0xFFFFFFFFFFFFFFFFull
#define FULLM  0xFFFFFFFFu

// ---------------- device scratch ----------------
__device__ unsigned long long g_skey[NCLS * SORTN];   // sorted keys per class
__device__ float4             g_sbox[NCLS * NBOX];    // clipped boxes in sorted order
__device__ int                g_m[NCLS];              // valid count per class
__device__ unsigned int       g_mask[NCLS * NW * NBOX]; // [class][word][row]
__device__ unsigned long long g_selkey[NSEL];         // per class: sorted kept top-100 (pad)
__device__ unsigned int       g_maxBits = 0u;
__device__ unsigned int       g_maxCnt  = 0u;
__device__ unsigned int       g_ready[NCLS];          // per-class sort-published flags
__device__ unsigned int       g_tile[NCLS];           // mask-tile completion counters
__device__ unsigned int       g_done    = 0u;
__device__ unsigned int       g_done2   = 0u;

// descending-sortable mapping (ascending u64 sort -> descending float score)
__device__ __forceinline__ unsigned int ord_desc(float f) {
    unsigned int u = __float_as_uint(f);
    unsigned int m = (u & 0x80000000u) ? ~u : (u | 0x80000000u);
    return ~m;
}
__device__ __forceinline__ float inv_ord(unsigned int o) {
    unsigned int m = ~o;
    unsigned int u = (m & 0x80000000u) ? (m & 0x7FFFFFFFu) : ~m;
    return __uint_as_float(u);
}
__device__ __forceinline__ unsigned long long shfl_xor_u64(unsigned long long v, int jj) {
    unsigned int lo = (unsigned int)v, hi = (unsigned int)(v >> 32);
    lo = __shfl_xor_sync(FULLM, lo, jj);
    hi = __shfl_xor_sync(FULLM, hi, jj);
    return ((unsigned long long)hi << 32) | lo;
}
__device__ __forceinline__ unsigned long long uminll(unsigned long long a, unsigned long long b) { return a < b ? a : b; }
__device__ __forceinline__ unsigned long long umaxll(unsigned long long a, unsigned long long b) { return a > b ? a : b; }
// sign-extend lowest bit to full mask: 0 -> 0x0, 1 -> 0xFFFFFFFF (single SGXT)
__device__ __forceinline__ unsigned int bit0_mask(unsigned int x) {
    unsigned int r;
    asm("szext.clamp.s32 %0, %1, 1;" : "=r"(r) : "r"(x));
    return r;
}

// ================= single fused kernel: sorter prefix + mask + greedy + merge =============
__global__ void __launch_bounds__(512, 2)
kAll(const float* __restrict__ boxes, const float* __restrict__ scores,
     const int* __restrict__ pred_cls, float* __restrict__ out)
{
    // buf1: sorter s_cbox -> mask s_b/s_a -> elected s_mask (phases disjoint in time)
    __shared__ __align__(16) unsigned char buf1[NBOX * NW * 4];     // 20.8 KB
    __shared__ __align__(16) unsigned long long s_sel[NSEL];        // 16 KB (elected only)
    __shared__ __align__(16) unsigned long long s_skey[SORTN];      // 4 KB (sort buf / key stage)
    __shared__ unsigned int s_wmax[16];
    __shared__ float        s_shift;
    __shared__ int          s_elect;

    float4*       s_cbox = reinterpret_cast<float4*>(buf1);                    // sorter phase
    float4*       s_b    = reinterpret_cast<float4*>(buf1);                    // mask phase
    float*        s_a    = reinterpret_cast<float*>(buf1 + NBOX * 16);         // mask phase
    unsigned int* s_mask = reinterpret_cast<unsigned int*>(buf1);              // elected phase

    const int c    = blockIdx.y;               // class
    const int ty   = blockIdx.x;               // 32-row tile 0..12 (ty==0 also sorts)
    const int tid  = threadIdx.x;
    const int wd   = tid >> 5, lane = tid & 31;

    // ---------------- sorter prefix (ty == 0): k1 body, publishes before any spin --------
    if (ty == 0) {
        float lmax = 0.0f;
        bool  valid = false;
        unsigned long long v = SENTK;
        if (tid < NBOX) {
            float4 bx = reinterpret_cast<const float4*>(boxes)[c * NBOX + tid];
            float2 sc = reinterpret_cast<const float2*>(scores)[c * NBOX + tid];
            bool fin = isfinite(bx.x) && isfinite(bx.y) && isfinite(bx.z) && isfinite(bx.w)
                    && isfinite(sc.x) && isfinite(sc.y);
            float x1 = fminf(fmaxf(bx.x, 0.0f), IMGW);
            float y1 = fminf(fmaxf(bx.y, 0.0f), IMGH);
            float x2 = fminf(fmaxf(bx.z, 0.0f), IMGW);
            float y2 = fminf(fmaxf(bx.w, 0.0f), IMGH);
            valid = fin && (sc.x > 0.05f);
            float masked = valid ? sc.x : -CUDART_INF_F;
            unsigned int j = (unsigned int)(tid * NCLS + c);   // transposed index
            v = ((unsigned long long)ord_desc(masked) << 32) | j;
            s_cbox[tid] = make_float4(x1, y1, x2, y2);
            lmax = fmaxf(fmaxf(x1, x2), fmaxf(y1, y2));
        }
        unsigned int wb = __reduce_max_sync(FULLM, __float_as_uint(lmax));
        if (lane == 0) s_wmax[tid >> 5] = wb;
        const int ml = __syncthreads_count(valid);
        if (tid == 0) {
            unsigned int mx = 0;
            #pragma unroll
            for (int w = 0; w < 16; w++) mx = max(mx, s_wmax[w]);
            atomicMax(&g_maxBits, mx);
            __threadfence();
            atomicAdd(&g_maxCnt, 1u);           // published BEFORE sorting: no circular wait
        }

        // hybrid bitonic sort: smem stages jj>=32, shfl stages jj<=16
        for (int k = 2; k <= SORTN; k <<= 1) {
            for (int jj = k >> 1; jj >= 32; jj >>= 1) {
                s_skey[tid] = v;
                __syncthreads();
                unsigned long long p = s_skey[tid ^ jj];
                bool km = (((tid & k) == 0) == ((tid & jj) == 0));
                v = km ? uminll(v, p) : umaxll(v, p);
                __syncthreads();
            }
            int j0 = (k >> 1) < 16 ? (k >> 1) : 16;
            for (int jj = j0; jj >= 1; jj >>= 1) {
                unsigned long long p = shfl_xor_u64(v, jj);
                bool km = (((tid & k) == 0) == ((tid & jj) == 0));
                v = km ? uminll(v, p) : umaxll(v, p);
            }
        }

        g_skey[c * SORTN + tid] = v;
        if (tid < ml) {
            unsigned int j = (unsigned int)v;
            int b = (int)(j / NCLS);
            g_sbox[c * NBOX + tid] = s_cbox[b];
        }
        if (tid == 0) g_m[c] = ml;

        // class-0 sorter pre-writes ALL default output rows
        if (c == 0) {
            if (tid < 4 * TOPK) out[tid] = 0.0f;              // boxes
            if (tid < TOPK) {
                out[4 * TOPK + tid] = 0.0f;                   // scores
                out[5 * TOPK + tid] = -1.0f;                  // cls
                out[6 * TOPK + tid] = 0.0f;                   // valid
            }
        }

        __threadfence();                        // each thread publishes its own stores
        __syncthreads();
        if (tid == 0) atomicExch(&g_ready[c], 1u);
    }

    // ---------------- common path: wait for shift prerequisites --------------------------
    if (tid == 0) {
        volatile unsigned int* vr = &g_ready[c];
        while (*vr == 0u) { }
        volatile unsigned int* vc2 = &g_maxCnt;
        while (*vc2 < (unsigned)NCLS) { }
        __threadfence();
        unsigned int mv = *(volatile unsigned int*)&g_maxBits;
        s_shift = __fmul_rn((float)c, __fadd_rn(__uint_as_float(mv), 1.0f));
    }
    __syncthreads();
    const int   m     = g_m[c];
    const float shift = s_shift;

    // triangular staging: this block only reads boxes t >= 32*ty (j > i >= 32ty)
    for (int t = 32 * ty + tid; t < NBOX; t += 512) {
        float4 bx = g_sbox[c * NBOX + t];
        float4 sb = make_float4(__fadd_rn(bx.x, shift), __fadd_rn(bx.y, shift),
                                __fadd_rn(bx.z, shift), __fadd_rn(bx.w, shift));
        s_b[t] = sb;
        s_a[t] = __fmul_rn(__fsub_rn(sb.z, sb.x), __fsub_rn(sb.w, sb.y));
    }
    __syncthreads();

    // this block's 32-row mask tile (warps 0..12 carry words 0..12)
    // "iou > 0.5" division-free: inter > 0.5*uni (uni >= 0 provable; uni=0 => inter=0)
    {
        const int i = ty * 32 + lane;
        if (wd < NW && i < m) {
            unsigned int bits = 0;
            const int lo = wd * 32;
            const int hi = min(m, lo + 32);
            const int st = max(lo, i + 1);
            if (st < hi) {
                float4 bi = s_b[i];
                float  ai = s_a[i];
                #pragma unroll 4
                for (int jd = st; jd < hi; jd++) {
                    float4 bj = s_b[jd];
                    float iw = fmaxf(__fsub_rn(fminf(bi.z, bj.z), fmaxf(bi.x, bj.x)), 0.0f);
                    float ih = fmaxf(__fsub_rn(fminf(bi.w, bj.w), fmaxf(bi.y, bj.y)), 0.0f);
                    float inter = __fmul_rn(iw, ih);
                    float uni = __fsub_rn(__fadd_rn(ai, s_a[jd]), inter);
                    if (inter > __fmul_rn(0.5f, uni)) bits |= 1u << (jd - lo);
                }
            }
            g_mask[(c * NW + wd) * NBOX + i] = bits;   // coalesced (lane = row)
        }
    }
    __threadfence();                               // release mask stores
    __syncthreads();
    if (tid == 0) {
        unsigned int r = atomicAdd(&g_tile[c], 1u);
        s_elect = (r == NTILE - 1) ? 1 : 0;        // last tile of this class proceeds
    }
    __syncthreads();
    if (!s_elect) return;

    // ================= elected block (one per class) =================
    __threadfence();                               // acquire peers' mask stores
    for (int t = tid; t < NW * NBOX; t += 512) {   // transposed reload, coalesced reads
        int w = t / NBOX;
        int i = t - w * NBOX;
        if (i < m) s_mask[i * NW + w] = g_mask[(c * NW + w) * NBOX + i];
    }
    for (int t = tid; t < SORTN; t += 512) s_skey[t] = g_skey[c * SORTN + t];
    __syncthreads();

    // greedy scan (warp 0): shifted-state chain, 2 dependent ops per row
    if (tid < 32) {
        const int rlane = (lane < NW) ? lane : (NW - 1);
        unsigned int mysup = 0;                    // lane w owns rows [32w, 32w+32)
        const int nb = (m + 31) >> 5;
        for (int b = 0; b < nb; b++) {
            const int base = b << 5;
            const int rows = min(32, m - base);
            unsigned int pad = (rows < 32) ? (FULLM << rows) : 0u;
            unsigned int curs = __shfl_sync(FULLM, mysup, b) | pad;
            unsigned int wreg[32];
            #pragma unroll
            for (int q = 0; q < 32; q++)
                wreg[q] = (q < rows) ? s_mask[(base + q) * NW + b] : 0u;
            #pragma unroll
            for (int q = 0; q < 32; q++) {
                int rr = min(base + q, NBOX - 1);                  // safe smem index
                unsigned int row = s_mask[rr * NW + rlane];        // off-chain LDS
                unsigned int Wq  = (q < 31) ? (wreg[q] >> (q + 1)) : 0u;  // off-chain
                unsigned int take = bit0_mask(curs);               // chain lvl 1 (SGXT)
                curs = (curs >> 1) | (Wq & ~take);                 // chain lvl 2
                mysup |= row & ~take;                              // off-chain LOP3
            }
        }
        int cnt = 0;
        for (int bs = 0; bs < m; bs += 32) {
            int t = bs + lane;
            unsigned int supw = __shfl_sync(FULLM, mysup, t >> 5);
            bool kept = (t < m) && !((supw >> (t & 31)) & 1u);
            unsigned int bal = __ballot_sync(FULLM, kept);
            int pos = cnt + __popc(bal & ((1u << lane) - 1u));
            if (kept && pos < TOPK) g_selkey[c * TOPK + pos] = s_skey[t];
            cnt += __popc(bal);
        }
        cnt = min(cnt, TOPK);
        for (int p = cnt + lane; p < TOPK; p += 32) g_selkey[c * TOPK + p] = SENTK;
        __threadfence();                           // publish selkey stores
        __syncwarp();
        if (lane == 0) atomicAdd(&g_done, 1u);
    }
    __syncthreads();

    // rendezvous: all 20 classes' selkey visible (20 pollers only)
    if (tid == 0) {
        volatile unsigned int* vd = &g_done;
        while (*vd < (unsigned)NCLS) { }
        __threadfence();
    }
    __syncthreads();

    // load all 2000 candidates (512 threads -> 4 loads each, high MLP)
    for (int t = tid; t < NSEL; t += 512) s_sel[t] = g_selkey[t];
    __syncthreads();

    // merge-by-rank: rank own class's kept keys against the other 19 sorted lists
    if (tid < TOPK) {
        unsigned long long e = s_sel[c * TOPK + tid];
        if (e != SENTK) {
            int rank = tid;                        // position within own sorted list
            #pragma unroll
            for (int c2 = 0; c2 < NCLS; c2++) {
                if (c2 == c) continue;
                const unsigned long long* seg = s_sel + c2 * TOPK;
                int lo = 0;                        // lower_bound: #elements < e
                #pragma unroll
                for (int s = 64; s > 0; s >>= 1) {
                    int p = lo + s;
                    if (p <= TOPK && seg[p - 1] < e) lo = p;
                }
                rank += lo;
            }
            if (rank < TOPK) {
                unsigned int j = (unsigned int)e;
                int cc = (int)(j % NCLS);
                int b  = (int)(j / NCLS);
                int i  = cc * NBOX + b;
                float4 bx = reinterpret_cast<const float4*>(boxes)[i];
                out[rank * 4 + 0] = fminf(fmaxf(bx.x, 0.0f), IMGW);
                out[rank * 4 + 1] = fminf(fmaxf(bx.y, 0.0f), IMGH);
                out[rank * 4 + 2] = fminf(fmaxf(bx.z, 0.0f), IMGW);
                out[rank * 4 + 3] = fminf(fmaxf(bx.w, 0.0f), IMGH);
                out[4 * TOPK + rank] = inv_ord((unsigned int)(e >> 32));
                out[5 * TOPK + rank] = (float)pred_cls[i];
                out[6 * TOPK + rank] = 1.0f;
            }
        }
    }

    // last finisher resets ALL globals for the next graph replay
    __syncthreads();
    if (tid == 0) {
        unsigned int r2 = atomicAdd(&g_done2, 1u);
        if (r2 == NCLS - 1) {
            g_maxBits = 0u;
            g_maxCnt  = 0u;
            g_done    = 0u;
            g_done2   = 0u;
            #pragma unroll
            for (int c2 = 0; c2 < NCLS; c2++) { g_tile[c2] = 0u; g_ready[c2] = 0u; }
            __threadfence();
        }
    }
}

// ---------------- launch ----------------
extern "C" void kernel_launch(void* const* d_in, const int* in_sizes, int n_in,
                              void* d_out, int out_size) {
    const int*   pred_cls = (const int*)d_in[0];
    const float* boxes    = (const float*)d_in[1];
    const float* scores   = (const float*)d_in[2];
    float* out = (float*)d_out;

    kAll<<<dim3(NTILE, NCLS), 512>>>(boxes, scores, pred_cls, out);
}

// round 17
// speedup vs baseline: 1.0094x; 1.0094x over previous
#include <cuda_runtime.h>
#include <math_constants.h>

#define NCLS   20
#define NBOX   400
#define SORTN  512
#define IMGW   1333.0f
#define IMGH   800.0f
#define TOPK   100
#define NSEL   (NCLS * TOPK)     // 2000
#define NW     13                // 400 bits -> 13 u32 words
#define NTILE  13                // 13 x 32 rows = 416 >= 400
#define SENTK  0xFFFFFFFFFFFFFFFFull
#define FULLM  0xFFFFFFFFu

// ---------------- device scratch ----------------
__device__ unsigned long long g_skey[NCLS * SORTN];   // sorted keys per class
__device__ float4             g_sbox[NCLS * NBOX];    // clipped boxes in sorted order
__device__ int                g_m[NCLS];              // valid count per class
__device__ unsigned int       g_mask[NCLS * NW * NBOX]; // [class][word][row]; rows>=m stay 0
__device__ unsigned long long g_selkey[NSEL];         // per class: sorted kept top-100 (pad)
__device__ unsigned int       g_maxBits = 0u;
__device__ unsigned int       g_tile[NCLS];           // mask-tile completion counters
__device__ unsigned int       g_done    = 0u;
__device__ unsigned int       g_done2   = 0u;

// descending-sortable mapping (ascending u64 sort -> descending float score)
__device__ __forceinline__ unsigned int ord_desc(float f) {
    unsigned int u = __float_as_uint(f);
    unsigned int m = (u & 0x80000000u) ? ~u : (u | 0x80000000u);
    return ~m;
}
__device__ __forceinline__ float inv_ord(unsigned int o) {
    unsigned int m = ~o;
    unsigned int u = (m & 0x80000000u) ? (m & 0x7FFFFFFFu) : ~m;
    return __uint_as_float(u);
}
__device__ __forceinline__ unsigned long long shfl_xor_u64(unsigned long long v, int jj) {
    unsigned int lo = (unsigned int)v, hi = (unsigned int)(v >> 32);
    lo = __shfl_xor_sync(FULLM, lo, jj);
    hi = __shfl_xor_sync(FULLM, hi, jj);
    return ((unsigned long long)hi << 32) | lo;
}
__device__ __forceinline__ unsigned long long uminll(unsigned long long a, unsigned long long b) { return a < b ? a : b; }
__device__ __forceinline__ unsigned long long umaxll(unsigned long long a, unsigned long long b) { return a > b ? a : b; }
// sign-extend lowest bit to full mask: 0 -> 0x0, 1 -> 0xFFFFFFFF (single SGXT)
__device__ __forceinline__ unsigned int bit0_mask(unsigned int x) {
    unsigned int r;
    asm("szext.clamp.s32 %0, %1, 1;" : "=r"(r) : "r"(x));
    return r;
}

// ---------------- k1: per-class load/clip/key + hybrid bitonic sort (champion verbatim) --
__global__ void __launch_bounds__(SORTN) k1(const float* __restrict__ boxes,
                                            const float* __restrict__ scores,
                                            float* __restrict__ out) {
    __shared__ unsigned long long skey[SORTN];
    __shared__ float4       s_cbox[NBOX];
    __shared__ unsigned int s_wmax[16];

    const int cls = blockIdx.x, tid = threadIdx.x, lane = tid & 31;

    float lmax = 0.0f;
    bool  valid = false;
    unsigned long long v = SENTK;
    if (tid < NBOX) {
        float4 bx = reinterpret_cast<const float4*>(boxes)[cls * NBOX + tid];
        float2 sc = reinterpret_cast<const float2*>(scores)[cls * NBOX + tid];
        bool fin = isfinite(bx.x) && isfinite(bx.y) && isfinite(bx.z) && isfinite(bx.w)
                && isfinite(sc.x) && isfinite(sc.y);
        float x1 = fminf(fmaxf(bx.x, 0.0f), IMGW);
        float y1 = fminf(fmaxf(bx.y, 0.0f), IMGH);
        float x2 = fminf(fmaxf(bx.z, 0.0f), IMGW);
        float y2 = fminf(fmaxf(bx.w, 0.0f), IMGH);
        valid = fin && (sc.x > 0.05f);
        float masked = valid ? sc.x : -CUDART_INF_F;
        unsigned int j = (unsigned int)(tid * NCLS + cls);       // transposed index
        v = ((unsigned long long)ord_desc(masked) << 32) | j;
        s_cbox[tid] = make_float4(x1, y1, x2, y2);
        lmax = fmaxf(fmaxf(x1, x2), fmaxf(y1, y2));
    }
    unsigned int wb = __reduce_max_sync(FULLM, __float_as_uint(lmax));
    if (lane == 0) s_wmax[tid >> 5] = wb;
    const int m = __syncthreads_count(valid);
    if (tid == 0) {
        unsigned int mx = 0;
        #pragma unroll
        for (int w = 0; w < 16; w++) mx = max(mx, s_wmax[w]);
        atomicMax(&g_maxBits, mx);
    }

    // hybrid bitonic sort: smem stages jj>=32, shfl stages jj<=16
    for (int k = 2; k <= SORTN; k <<= 1) {
        for (int jj = k >> 1; jj >= 32; jj >>= 1) {
            skey[tid] = v;
            __syncthreads();
            unsigned long long p = skey[tid ^ jj];
            bool km = (((tid & k) == 0) == ((tid & jj) == 0));
            v = km ? uminll(v, p) : umaxll(v, p);
            __syncthreads();
        }
        int j0 = (k >> 1) < 16 ? (k >> 1) : 16;
        for (int jj = j0; jj >= 1; jj >>= 1) {
            unsigned long long p = shfl_xor_u64(v, jj);
            bool km = (((tid & k) == 0) == ((tid & jj) == 0));
            v = km ? uminll(v, p) : umaxll(v, p);
        }
    }

    g_skey[cls * SORTN + tid] = v;
    if (tid < m) {
        unsigned int j = (unsigned int)v;
        int b = (int)(j / NCLS);
        g_sbox[cls * NBOX + tid] = s_cbox[b];
    }
    if (tid == 0) g_m[cls] = m;

    // class-0 block pre-writes ALL default output rows; kB overwrites ranked rows
    if (cls == 0) {
        if (tid < 4 * TOPK) out[tid] = 0.0f;                  // boxes
        if (tid < TOPK) {
            out[4 * TOPK + tid] = 0.0f;                       // scores
            out[5 * TOPK + tid] = -1.0f;                      // cls
            out[6 * TOPK + tid] = 0.0f;                       // valid
        }
    }
}

// ---------------- kB: mask tile + last-tile election -> greedy + merge + output ----------
__global__ void __launch_bounds__(512) kB(const float* __restrict__ boxes,
                                          const int* __restrict__ pred_cls,
                                          float* __restrict__ out) {
    // buf1: s_b+s_a during mask phase; s_mask for elected block (disjoint in time)
    __shared__ __align__(16) unsigned char buf1[NBOX * NW * 4];     // 20.8 KB
    __shared__ __align__(16) unsigned long long s_sel[NSEL];        // 16 KB (elected only)
    __shared__ __align__(16) unsigned long long s_skey[SORTN];      // 4 KB (elected only)
    __shared__ int s_elect;

    float4*       s_b    = reinterpret_cast<float4*>(buf1);                    // [NBOX]
    float*        s_a    = reinterpret_cast<float*>(buf1 + NBOX * 16);         // [NBOX]
    unsigned int* s_mask = reinterpret_cast<unsigned int*>(buf1);              // [NBOX*NW] row-major

    const int c   = blockIdx.y;                    // class
    const int ty  = blockIdx.x;                    // 32-row tile 0..12
    const int tid = threadIdx.x;
    const int wd  = tid >> 5, lane = tid & 31;
    const int m   = g_m[c];                        // overlaps with staging below

    const float offv  = __fadd_rn(__uint_as_float(g_maxBits), 1.0f);
    const float shift = __fmul_rn((float)c, offv);

    // triangular staging: this block only ever reads boxes t >= 32*ty (j > i >= 32ty)
    for (int t = 32 * ty + tid; t < NBOX; t += 512) {
        float4 bx = g_sbox[c * NBOX + t];
        float4 sb = make_float4(__fadd_rn(bx.x, shift), __fadd_rn(bx.y, shift),
                                __fadd_rn(bx.z, shift), __fadd_rn(bx.w, shift));
        s_b[t] = sb;
        s_a[t] = __fmul_rn(__fsub_rn(sb.z, sb.x), __fsub_rn(sb.w, sb.y));
    }
    __syncthreads();

    // this block's 32-row mask tile (warps 0..12 carry words 0..12)
    // "iou > 0.5" division-free: inter > 0.5*uni (uni >= 0 provable; uni=0 => inter=0)
    {
        const int i = ty * 32 + lane;
        if (wd < NW && i < m) {
            unsigned int bits = 0;
            const int lo = wd * 32;
            const int hi = min(m, lo + 32);
            const int st = max(lo, i + 1);
            if (st < hi) {
                float4 bi = s_b[i];
                float  ai = s_a[i];
                #pragma unroll 4
                for (int jd = st; jd < hi; jd++) {
                    float4 bj = s_b[jd];
                    float iw = fmaxf(__fsub_rn(fminf(bi.z, bj.z), fmaxf(bi.x, bj.x)), 0.0f);
                    float ih = fmaxf(__fsub_rn(fminf(bi.w, bj.w), fmaxf(bi.y, bj.y)), 0.0f);
                    float inter = __fmul_rn(iw, ih);
                    float uni = __fsub_rn(__fadd_rn(ai, s_a[jd]), inter);
                    if (inter > __fmul_rn(0.5f, uni)) bits |= 1u << (jd - lo);
                }
            }
            g_mask[(c * NW + wd) * NBOX + i] = bits;   // coalesced (lane = row)
        }
    }
    __threadfence();                               // release mask stores
    __syncthreads();
    if (tid == 0) {
        unsigned int r = atomicAdd(&g_tile[c], 1u);
        s_elect = (r == NTILE - 1) ? 1 : 0;        // last tile of this class proceeds
    }
    __syncthreads();
    if (!s_elect) return;

    // ================= elected block (one per class) =================
    __threadfence();                               // acquire peers' mask stores
    // guard-free transposed reload: rows >= m in g_mask are never written (zero since
    // module load) -> deterministic zeros; the greedy's pad-take masks them anyway.
    for (int t = tid; t < NW * NBOX; t += 512) {
        int w = t / NBOX;
        int i = t - w * NBOX;
        s_mask[i * NW + w] = g_mask[(c * NW + w) * NBOX + i];
    }
    for (int t = tid; t < SORTN; t += 512) s_skey[t] = g_skey[c * SORTN + t];
    __syncthreads();

    // greedy scan (warp 0): shifted-state chain, 2 dependent ops per row
    if (tid < 32) {
        const int rlane = (lane < NW) ? lane : (NW - 1);
        unsigned int mysup = 0;                    // lane w owns rows [32w, 32w+32)
        const int nb = (m + 31) >> 5;
        for (int b = 0; b < nb; b++) {
            const int base = b << 5;
            const int rows = min(32, m - base);
            unsigned int pad = (rows < 32) ? (FULLM << rows) : 0u;
            unsigned int curs = __shfl_sync(FULLM, mysup, b) | pad;
            unsigned int wreg[32];
            #pragma unroll
            for (int q = 0; q < 32; q++)
                wreg[q] = (q < rows) ? s_mask[(base + q) * NW + b] : 0u;
            #pragma unroll
            for (int q = 0; q < 32; q++) {
                int rr = min(base + q, NBOX - 1);                  // safe smem index
                unsigned int row = s_mask[rr * NW + rlane];        // off-chain LDS
                unsigned int Wq  = (q < 31) ? (wreg[q] >> (q + 1)) : 0u;  // off-chain
                unsigned int take = bit0_mask(curs);               // chain lvl 1 (SGXT)
                curs = (curs >> 1) | (Wq & ~take);                 // chain lvl 2
                mysup |= row & ~take;                              // off-chain LOP3
            }
        }
        int cnt = 0;
        for (int bs = 0; bs < m; bs += 32) {
            int t = bs + lane;
            unsigned int supw = __shfl_sync(FULLM, mysup, t >> 5);
            bool kept = (t < m) && !((supw >> (t & 31)) & 1u);
            unsigned int bal = __ballot_sync(FULLM, kept);
            int pos = cnt + __popc(bal & ((1u << lane) - 1u));
            if (kept && pos < TOPK) g_selkey[c * TOPK + pos] = s_skey[t];
            cnt += __popc(bal);
        }
        cnt = min(cnt, TOPK);
        for (int p = cnt + lane; p < TOPK; p += 32) g_selkey[c * TOPK + p] = SENTK;
        __threadfence();                           // publish selkey stores
        __syncwarp();
        if (lane == 0) atomicAdd(&g_done, 1u);
    }
    __syncthreads();

    // preload OWN class segment before the spin (overlaps rendezvous latency;
    // own segment is complete: this block wrote it before arriving at g_done)
    for (int t = tid; t < TOPK; t += 512) s_sel[c * TOPK + t] = g_selkey[c * TOPK + t];

    // rendezvous: all 20 classes' selkey visible (20 pollers only)
    if (tid == 0) {
        volatile unsigned int* vd = &g_done;
        while (*vd < (unsigned)NCLS) { }
        __threadfence();
    }
    __syncthreads();

    // load the other 19 classes' candidates (512 threads, high MLP)
    for (int t = tid; t < NSEL; t += 512) {
        if (t < c * TOPK || t >= (c + 1) * TOPK) s_sel[t] = g_selkey[t];
    }
    __syncthreads();

    // merge-by-rank: rank own class's kept keys against the other 19 sorted lists
    if (tid < TOPK) {
        unsigned long long e = s_sel[c * TOPK + tid];
        if (e != SENTK) {
            int rank = tid;                        // position within own sorted list
            #pragma unroll
            for (int c2 = 0; c2 < NCLS; c2++) {
                if (c2 == c) continue;
                const unsigned long long* seg = s_sel + c2 * TOPK;
                int lo = 0;                        // lower_bound: #elements < e
                #pragma unroll
                for (int s = 64; s > 0; s >>= 1) {
                    int p = lo + s;
                    if (p <= TOPK && seg[p - 1] < e) lo = p;
                }
                rank += lo;
            }
            if (rank < TOPK) {
                unsigned int j = (unsigned int)e;
                int cc = (int)(j % NCLS);
                int b  = (int)(j / NCLS);
                int i  = cc * NBOX + b;
                float4 bx = reinterpret_cast<const float4*>(boxes)[i];
                out[rank * 4 + 0] = fminf(fmaxf(bx.x, 0.0f), IMGW);
                out[rank * 4 + 1] = fminf(fmaxf(bx.y, 0.0f), IMGH);
                out[rank * 4 + 2] = fminf(fmaxf(bx.z, 0.0f), IMGW);
                out[rank * 4 + 3] = fminf(fmaxf(bx.w, 0.0f), IMGH);
                out[4 * TOPK + rank] = inv_ord((unsigned int)(e >> 32));
                out[5 * TOPK + rank] = (float)pred_cls[i];
                out[6 * TOPK + rank] = 1.0f;
            }
        }
    }

    // last finisher resets globals for the next graph replay
    __syncthreads();
    if (tid == 0) {
        unsigned int r2 = atomicAdd(&g_done2, 1u);
        if (r2 == NCLS - 1) {
            g_maxBits = 0u;
            g_done    = 0u;
            g_done2   = 0u;
            #pragma unroll
            for (int c2 = 0; c2 < NCLS; c2++) g_tile[c2] = 0u;
            __threadfence();
        }
    }
}

// ---------------- launch ----------------
extern "C" void kernel_launch(void* const* d_in, const int* in_sizes, int n_in,
                              void* d_out, int out_size) {
    const int*   pred_cls = (const int*)d_in[0];
    const float* boxes    = (const float*)d_in[1];
    const float* scores   = (const float*)d_in[2];
    float* out = (float*)d_out;

    k1<<<NCLS, SORTN>>>(boxes, scores, out);
    kB<<<dim3(NTILE, NCLS), 512>>>(boxes, pred_cls, out);
}